// round 1
// baseline (speedup 1.0000x reference)
#include <cuda_runtime.h>
#include <math.h>

#define T_DIM 512
#define B_DIM 64
#define I_DIM 512
#define H_DIM 512
#define BH (B_DIM * H_DIM)          // 32768
#define NBLK 128                    // persistent blocks in recurrent kernel
#define NKC 16                      // split-K chunks (512/32)

// ---------------- scratch (no allocations allowed) ----------------
__device__ float g_xz[T_DIM * B_DIM];
__device__ float g_xr[T_DIM * B_DIM];
__device__ float g_part[NKC * B_DIM * H_DIM];   // [kc][b][h] partial matvec, 2MB
__device__ float g_azp[NKC * B_DIM];
__device__ float g_arp[NKC * B_DIM];
__device__ unsigned int g_cnt;
__device__ unsigned int g_gen;

// ---------------- grid-wide barrier (all NBLK blocks resident) ----------------
__device__ __forceinline__ void grid_sync() {
    __threadfence();
    __syncthreads();
    if (threadIdx.x == 0) {
        unsigned int gen = *(volatile unsigned int*)&g_gen;
        if (atomicAdd(&g_cnt, 1u) == NBLK - 1) {
            g_cnt = 0;
            __threadfence();
            *(volatile unsigned int*)&g_gen = gen + 1;
        } else {
            while (*(volatile unsigned int*)&g_gen == gen) { }
        }
    }
    __syncthreads();
    __threadfence();
}

// ---------------- K1: xz/xr gate input projections ----------------
// one warp per (t,b): two length-512 dots against zt_w_w / rt_w_w
__global__ __launch_bounds__(256) void k_gates_x(
    const float* __restrict__ inp,
    const float* __restrict__ zw, const float* __restrict__ zb,
    const float* __restrict__ rw, const float* __restrict__ rb)
{
    int w = (blockIdx.x * blockDim.x + threadIdx.x) >> 5;
    int lane = threadIdx.x & 31;
    if (w >= T_DIM * B_DIM) return;
    const float4* ip = (const float4*)(inp + (size_t)w * I_DIM);
    const float4* zp = (const float4*)zw;
    const float4* rp = (const float4*)rw;
    float az = 0.f, ar = 0.f;
#pragma unroll
    for (int i = 0; i < 4; i++) {
        float4 v = ip[i * 32 + lane];
        float4 a = zp[i * 32 + lane];
        float4 b = rp[i * 32 + lane];
        az += v.x * a.x + v.y * a.y + v.z * a.z + v.w * a.w;
        ar += v.x * b.x + v.y * b.y + v.z * b.z + v.w * b.w;
    }
#pragma unroll
    for (int o = 16; o > 0; o >>= 1) {
        az += __shfl_down_sync(0xffffffffu, az, o);
        ar += __shfl_down_sync(0xffffffffu, ar, o);
    }
    if (lane == 0) {
        g_xz[w] = az + zb[0];
        g_xr[w] = ar + rb[0];
    }
}

// ---------------- K2: xn = input @ h_w_w^T + h_w_b  -> written into out[t] ----------------
// C[M=32768, N=512], fp32 tiled GEMM: BM=BN=64, BK=16, 256 threads, 4x4 micro-tile
__global__ __launch_bounds__(256) void k_xn(
    const float* __restrict__ A,     // [32768, 512] input flattened
    const float* __restrict__ W,     // [512, 512] h_w_w (row-major [o][i])
    const float* __restrict__ bias,  // [512]
    float* __restrict__ C)           // [32768, 512] = d_out first part
{
    __shared__ float As[64 * 16];    // [m][k]
    __shared__ float Ws[16 * 64];    // [k][n]
    const int bm = blockIdx.y * 64;
    const int bn = blockIdx.x * 64;
    const int tid = threadIdx.x;
    const int tx = tid & 15;          // n quad
    const int ty = tid >> 4;          // m quad
    const int lrow = tid >> 2;        // 0..63
    const int lc4 = (tid & 3) * 4;    // 0,4,8,12

    float acc[4][4] = {};
    for (int k0 = 0; k0 < 512; k0 += 16) {
        float4 av = *(const float4*)(A + (size_t)(bm + lrow) * 512 + k0 + lc4);
        float4 wv = *(const float4*)(W + (size_t)(bn + lrow) * 512 + k0 + lc4);
        __syncthreads();
        As[lrow * 16 + lc4 + 0] = av.x;
        As[lrow * 16 + lc4 + 1] = av.y;
        As[lrow * 16 + lc4 + 2] = av.z;
        As[lrow * 16 + lc4 + 3] = av.w;
        Ws[(lc4 + 0) * 64 + lrow] = wv.x;
        Ws[(lc4 + 1) * 64 + lrow] = wv.y;
        Ws[(lc4 + 2) * 64 + lrow] = wv.z;
        Ws[(lc4 + 3) * 64 + lrow] = wv.w;
        __syncthreads();
#pragma unroll
        for (int k = 0; k < 16; k++) {
            float4 b4 = *(float4*)&Ws[k * 64 + tx * 4];
            float bb[4] = { b4.x, b4.y, b4.z, b4.w };
#pragma unroll
            for (int i = 0; i < 4; i++) {
                float a = As[(ty * 4 + i) * 16 + k];
                acc[i][0] += a * bb[0];
                acc[i][1] += a * bb[1];
                acc[i][2] += a * bb[2];
                acc[i][3] += a * bb[3];
            }
        }
    }
    float4 bv = *(const float4*)(bias + bn + tx * 4);
#pragma unroll
    for (int i = 0; i < 4; i++) {
        float4 o;
        o.x = acc[i][0] + bv.x;
        o.y = acc[i][1] + bv.y;
        o.z = acc[i][2] + bv.z;
        o.w = acc[i][3] + bv.w;
        *(float4*)(C + (size_t)(bm + ty * 4 + i) * 512 + bn + tx * 4) = o;
    }
}

// ---------------- K3: persistent recurrent scan ----------------
// 128 blocks = 8 h-groups (64 cols) x 16 K-chunks (32). Weight tile lives in SMEM
// for the whole scan. Per step: phase A (split-K partial matvec + gate partials),
// grid barrier, phase B (combine + gates + update, elementwise over 32768), barrier.
__global__ __launch_bounds__(256, 1) void k_recur(
    const float* __restrict__ hidden,
    const float* __restrict__ zu_w, const float* __restrict__ zu_b,
    const float* __restrict__ ru_w, const float* __restrict__ ru_b,
    const float* __restrict__ hu_w, const float* __restrict__ hu_b,
    float* __restrict__ out,          // [T][B][H], holds xn on entry, h_t on exit
    float* __restrict__ hfinal, int write_final)
{
    __shared__ float w_s[32 * 64];     // [k][j] transposed weight chunk
    __shared__ float h_s[64 * 36];     // [b][k] padded
    __shared__ float zu_s[512];
    __shared__ float ru_s[512];

    const int tid = threadIdx.x;
    const int bid = blockIdx.x;
    const int hg = bid & 7;            // h-group: cols [hg*64, hg*64+64)
    const int kc = bid >> 3;           // K-chunk: [kc*32, kc*32+32)
    const int h0 = hg * 64;
    const int k0 = kc * 32;
    const int tx = tid & 15;           // h' quad within group
    const int ty = tid >> 4;           // b quad

    // persistent weight tile (transposed for conflict-free float4 reads)
    for (int e = tid; e < 2048; e += 256) {
        int j = e >> 5, k = e & 31;
        w_s[k * 64 + j] = hu_w[(size_t)(h0 + j) * 512 + k0 + k];
    }
    for (int e = tid; e < 512; e += 256) {
        zu_s[e] = zu_w[e];
        ru_s[e] = ru_w[e];
    }
    const float zub = zu_b[0], rub = ru_b[0];

    // elementwise index for phase B (block-contiguous, coalesced)
    const int eidx = bid * 256 + tid;        // 0..32767
    const int eb = eidx >> 9;
    const int eh = eidx & 511;
    const float hub_e = hu_b[eh];
    __syncthreads();

    for (int t = 0; t < T_DIM; t++) {
        const float* hprev = (t == 0) ? hidden : (out + (size_t)(t - 1) * BH);

        // ---- phase A: load h chunk [64 b][32 k] ----
        for (int e = tid; e < 2048; e += 256) {
            int b = e >> 5, k = e & 31;
            h_s[b * 36 + k] = hprev[(size_t)b * 512 + k0 + k];
        }
        __syncthreads();

        // gate partials (only hg==0 blocks: 16 blocks cover 16 K-chunks)
        if (hg == 0 && tid < 64) {
            float az = 0.f, ar = 0.f;
#pragma unroll
            for (int k = 0; k < 32; k++) {
                float hv = h_s[tid * 36 + k];
                az += hv * zu_s[k0 + k];
                ar += hv * ru_s[k0 + k];
            }
            g_azp[kc * 64 + tid] = az;
            g_arp[kc * 64 + tid] = ar;
        }

        // split-K partial of h @ hu_w^T : 4x4 register tile per thread
        float acc[4][4] = {};
#pragma unroll
        for (int k = 0; k < 32; k++) {
            float4 wv = *(float4*)&w_s[k * 64 + tx * 4];
#pragma unroll
            for (int i = 0; i < 4; i++) {
                float hv = h_s[(ty * 4 + i) * 36 + k];
                acc[i][0] += hv * wv.x;
                acc[i][1] += hv * wv.y;
                acc[i][2] += hv * wv.z;
                acc[i][3] += hv * wv.w;
            }
        }
#pragma unroll
        for (int i = 0; i < 4; i++) {
            float4 v = make_float4(acc[i][0], acc[i][1], acc[i][2], acc[i][3]);
            *(float4*)&g_part[((size_t)kc * 64 + ty * 4 + i) * 512 + h0 + tx * 4] = v;
        }

        grid_sync();

        // ---- phase B: combine partials, gates, state update ----
        {
            float az = g_xz[t * 64 + eb] + zub;
            float ar = g_xr[t * 64 + eb] + rub;
#pragma unroll
            for (int kk = 0; kk < NKC; kk++) {
                az += g_azp[kk * 64 + eb];
                ar += g_arp[kk * 64 + eb];
            }
            float m = hub_e;
#pragma unroll
            for (int kk = 0; kk < NKC; kk++)
                m += g_part[((size_t)kk * 64 + eb) * 512 + eh];

            float z = 1.0f / (1.0f + expf(-az));
            float r = 1.0f / (1.0f + expf(-ar));
            float xn = out[(size_t)t * BH + eidx];                     // precomputed xn
            float hold = (t == 0) ? hidden[eidx] : out[(size_t)(t - 1) * BH + eidx];
            float n = tanhf(xn + m * r);
            out[(size_t)t * BH + eidx] = (1.0f - z) * n + z * hold;    // overwrite with h_t
        }

        grid_sync();
    }

    if (write_final)
        hfinal[eidx] = out[(size_t)(T_DIM - 1) * BH + eidx];
}

// ---------------- launcher ----------------
extern "C" void kernel_launch(void* const* d_in, const int* in_sizes, int n_in,
                              void* d_out, int out_size)
{
    const float* input  = (const float*)d_in[0];
    const float* hidden = (const float*)d_in[1];
    const float* zt_w_w = (const float*)d_in[2];
    const float* zt_w_b = (const float*)d_in[3];
    const float* zt_u_w = (const float*)d_in[4];
    const float* zt_u_b = (const float*)d_in[5];
    const float* rt_w_w = (const float*)d_in[6];
    const float* rt_w_b = (const float*)d_in[7];
    const float* rt_u_w = (const float*)d_in[8];
    const float* rt_u_b = (const float*)d_in[9];
    const float* h_w_w  = (const float*)d_in[10];
    const float* h_w_b  = (const float*)d_in[11];
    const float* h_u_w  = (const float*)d_in[12];
    const float* h_u_b  = (const float*)d_in[13];

    float* out = (float*)d_out;
    int wf = (out_size >= T_DIM * BH + BH) ? 1 : 0;
    float* hfin = out + (size_t)T_DIM * BH;

    // K1: gate input projections (independent of scan)
    k_gates_x<<<4096, 256>>>(input, zt_w_w, zt_w_b, rt_w_w, rt_w_b);
    // K2: xn GEMM written straight into d_out[t] slots
    k_xn<<<dim3(8, 512), 256>>>(input, h_w_w, h_w_b, out);
    // K3: persistent recurrent scan (reads xn from d_out, overwrites with h_t)
    k_recur<<<NBLK, 256>>>(hidden, zt_u_w, zt_u_b, rt_u_w, rt_u_b,
                           h_u_w, h_u_b, out, hfin, wf);
}